// round 7
// baseline (speedup 1.0000x reference)
#include <cuda_runtime.h>
#include <cstdint>

#define Bq 16
#define Tt 1024
#define Dd 512
#define Kk 1024
#define Qq 8
#define Nn (Bq*Tt)        // 16384 rows
#define MT 64             // rows per CTA
#define NT 128            // codes per tile
#define DC 32             // d-chunk
#define NTHR 256
#define NCTA (Nn/MT)      // 256
#define RSTRIDE 516       // residual row stride (floats), pad 4
#define CS2STRIDE 17      // code tile row stride in float2 (16 data + 1 pad)
#define REFINE_THR 4.0e-3f

// smem float counts
#define CS2_F (NT*CS2STRIDE*2)     // 4352
#define RS_F  (MT*RSTRIDE)         // 33024
#define SMEM_FLOATS (CS2_F + RS_F + MT + MT*4 + MT + MT)
#define SMEM_INTS   (MT + MT + MT + Qq*MT)
#define SMEM_BYTES  ((SMEM_FLOATS + SMEM_INTS)*4)

__device__ float g_cnorms[Qq*Kk];      // fast-path norms (accurate scheme)
__device__ float g_cnorms_em[Qq*Kk];   // emulated XLA-CPU order: sequential mul+add
__device__ float g_losspart[NCTA];

#define FMA2(acc, x, y) asm("fma.rn.f32x2 %0, %1, %2, %0;" : "+l"(acc) : "l"(x), "l"(y))

// ---------------------------------------------------------------- codebook norms
// fast norms: compensated (accurate; used only for fast candidate scores)
__global__ void __launch_bounds__(256) cnorm_kernel(const float* __restrict__ cb) {
    int idx = blockIdx.x * blockDim.x + threadIdx.x;
    if (idx >= Qq * Kk) return;
    const float* row = cb + (size_t)idx * Dd;
    float s = 0.f, comp = 0.f;
    #pragma unroll 4
    for (int d = 0; d < Dd; d++) {
        float v = __ldg(row + d);
        float p  = __fmul_rn(v, v);
        float ep = __fmaf_rn(v, v, -p);
        float t  = __fadd_rn(s, p);
        float bb = __fsub_rn(t, s);
        float es = __fadd_rn(__fsub_rn(s, __fsub_rn(t, bb)), __fsub_rn(p, bb));
        s = t;
        comp = __fadd_rn(comp, __fadd_rn(ep, es));
    }
    g_cnorms[idx] = __fadd_rn(s, comp);
}

// emulated norms: XLA:CPU reduce = strict sequential scalar  s = s + x*x  (no fma)
__global__ void __launch_bounds__(256) cnorm_em_kernel(const float* __restrict__ cb) {
    int idx = blockIdx.x * blockDim.x + threadIdx.x;
    if (idx >= Qq * Kk) return;
    const float* row = cb + (size_t)idx * Dd;
    float s = 0.f;
    for (int d = 0; d < Dd; d++) {
        float v = __ldg(row + d);
        s = __fadd_rn(s, __fmul_rn(v, v));
    }
    g_cnorms_em[idx] = s;
}

// ---------------------------------------------------------------- main RVQ
__global__ void __launch_bounds__(NTHR, 1) rvq_kernel(
    const float* __restrict__ z, const float* __restrict__ cb,
    float* __restrict__ out, int out_size)
{
    extern __shared__ float smf[];
    float2* cs2  = (float2*)smf;                 // [NT][CS2STRIDE] float2
    float*  rs   = smf + CS2_F;                  // [MT][RSTRIDE]
    float*  srr  = rs + RS_F;                    // [MT]
    float*  swp  = srr + MT;                     // [MT][4]
    float*  s1v  = swp + MT*4;                   // [MT]
    float*  s2v  = s1v + MT;                     // [MT]
    int*    s1i  = (int*)(s2v + MT);             // [MT]
    int*    s2i  = s1i + MT;                     // [MT]
    int*    sidx = s2i + MT;                     // [MT]
    int*    sall = sidx + MT;                    // [Qq][MT]

    const int tid  = threadIdx.x;
    const int lane = tid & 31;
    const int wid  = tid >> 5;
    const int row0 = blockIdx.x * MT;

    // ---- load z rows into smem + initial per-row ||r||^2 (fast scheme)
    {
        const int urow = tid >> 2, uq = tid & 3, d0 = uq * 128;
        const float4* zsrc = (const float4*)(z + (size_t)(row0 + urow) * Dd + d0);
        float4* rdst = (float4*)(rs + urow * RSTRIDE + d0);
        float ss = 0.f;
        #pragma unroll 8
        for (int j = 0; j < 32; j++) {
            float4 v = __ldg(zsrc + j);
            rdst[j] = v;
            ss = fmaf(v.x, v.x, ss); ss = fmaf(v.y, v.y, ss);
            ss = fmaf(v.z, v.z, ss); ss = fmaf(v.w, v.w, ss);
        }
        swp[urow * 4 + uq] = ss;
    }
    __syncthreads();
    if (tid < MT) srr[tid] = ((swp[tid*4] + swp[tid*4+1]) + swp[tid*4+2]) + swp[tid*4+3];
    __syncthreads();

    float loss_acc = 0.f;

    for (int q = 0; q < Qq; q++) {
        const float* cbq = cb + (size_t)q * Kk * Dd;
        const float* cnq = g_cnorms + q * Kk;

        // per-lane running top-2 per row
        float t1v[8], t2v[8]; int t1i[8], t2i[8];
        #pragma unroll
        for (int i = 0; i < 8; i++) {
            t1v[i] = 3.4e38f; t1i[i] = 0x7fffffff;
            t2v[i] = 3.4e38f; t2i[i] = 0x7ffffffe;
        }

        for (int nt = 0; nt < Kk / NT; nt++) {
            const int k0 = nt * NT;
            float cnv[4];
            #pragma unroll
            for (int j = 0; j < 4; j++) cnv[j] = __ldg(cnq + k0 + lane + 32*j);

            unsigned long long acc[8][4];
            #pragma unroll
            for (int i = 0; i < 8; i++)
                #pragma unroll
                for (int j = 0; j < 4; j++) acc[i][j] = 0ULL;

            for (int dc = 0; dc < Dd / DC; dc++) {
                __syncthreads();
                #pragma unroll
                for (int it = 0; it < 4; it++) {
                    int linI = tid + it * NTHR;             // 0..1023
                    int k = linI >> 3, d4 = linI & 7;
                    float4 v = __ldg((const float4*)(cbq + (size_t)(k0 + k) * Dd + dc*DC + d4*4));
                    cs2[k * CS2STRIDE + d4*2    ] = make_float2(v.x, v.y);
                    cs2[k * CS2STRIDE + d4*2 + 1] = make_float2(v.z, v.w);
                }
                __syncthreads();

                const unsigned long long* csu  = (const unsigned long long*)cs2;
                const unsigned long long* rbas = (const unsigned long long*)rs;
                #pragma unroll
                for (int dd = 0; dd < DC/2; dd++) {
                    unsigned long long rv[8];
                    #pragma unroll
                    for (int i = 0; i < 8; i++)
                        rv[i] = rbas[(wid*8 + i) * (RSTRIDE/2) + dc*(DC/2) + dd];
                    unsigned long long cv[4];
                    #pragma unroll
                    for (int j = 0; j < 4; j++)
                        cv[j] = csu[(lane + 32*j) * CS2STRIDE + dd];
                    #pragma unroll
                    for (int i = 0; i < 8; i++)
                        #pragma unroll
                        for (int j = 0; j < 4; j++)
                            FMA2(acc[i][j], rv[i], cv[j]);
                }
            }

            // ---- fast scores; insert into per-lane top-2
            #pragma unroll
            for (int i = 0; i < 8; i++) {
                float rr = srr[wid*8 + i];
                #pragma unroll
                for (int j = 0; j < 4; j++) {
                    unsigned int lo, hi;
                    asm("mov.b64 {%0,%1}, %2;" : "=r"(lo), "=r"(hi) : "l"(acc[i][j]));
                    float dot = __fadd_rn(__uint_as_float(lo), __uint_as_float(hi));
                    float s = __fadd_rn(__fsub_rn(rr, __fmul_rn(2.0f, dot)), cnv[j]);
                    int k = k0 + lane + 32*j;
                    if (s < t1v[i] || (s == t1v[i] && k < t1i[i])) {
                        t2v[i] = t1v[i]; t2i[i] = t1i[i];
                        t1v[i] = s;      t1i[i] = k;
                    } else if (s < t2v[i] || (s == t2v[i] && k < t2i[i])) {
                        t2v[i] = s; t2i[i] = k;
                    }
                }
            }
        }

        // ---- warp butterfly top-2 merge, write to smem
        #pragma unroll
        for (int i = 0; i < 8; i++) {
            float v1 = t1v[i]; int i1 = t1i[i];
            float v2 = t2v[i]; int i2 = t2i[i];
            #pragma unroll
            for (int off = 16; off > 0; off >>= 1) {
                float w1 = __shfl_xor_sync(0xffffffffu, v1, off);
                int   j1 = __shfl_xor_sync(0xffffffffu, i1, off);
                float w2 = __shfl_xor_sync(0xffffffffu, v2, off);
                int   j2 = __shfl_xor_sync(0xffffffffu, i2, off);
                if (w1 < v1 || (w1 == v1 && j1 < i1)) {
                    bool a_over_b2 = (v1 < w2 || (v1 == w2 && i1 < j2));
                    float nv2 = a_over_b2 ? v1 : w2;
                    int   ni2 = a_over_b2 ? i1 : j2;
                    v2 = nv2; i2 = ni2; v1 = w1; i1 = j1;
                } else if (w1 < v2 || (w1 == v2 && j1 < i2)) {
                    v2 = w1; i2 = j1;
                }
            }
            if (lane == 0) {
                s1v[wid*8+i] = v1; s1i[wid*8+i] = i1;
                s2v[wid*8+i] = v2; s2i[wid*8+i] = i2;
            }
        }
        __syncthreads();

        // ---- near-tie re-decision with EMULATED reference arithmetic
        // (XLA:CPU hypothesis: rr = sequential scalar s+x*x; dot = Eigen SGEMM
        //  strict ascending-k fma chain; score tree (rr - 2*dot) + cn.)
        if (tid < MT) {
            float v1 = s1v[tid]; int i1 = s1i[tid];
            float v2 = s2v[tid]; int i2 = s2i[tid];
            int chosen = i1;
            if (__fsub_rn(v2, v1) <= REFINE_THR) {
                const float* rrow = rs + tid * RSTRIDE;
                float rrE = 0.f;
                for (int d = 0; d < Dd; d++)
                    rrE = __fadd_rn(rrE, __fmul_rn(rrow[d], rrow[d]));
                const float* cA = cbq + (size_t)i1 * Dd;
                const float* cB = cbq + (size_t)i2 * Dd;
                float dA = 0.f, dB = 0.f;
                for (int d = 0; d < Dd; d++) dA = __fmaf_rn(rrow[d], __ldg(cA + d), dA);
                for (int d = 0; d < Dd; d++) dB = __fmaf_rn(rrow[d], __ldg(cB + d), dB);
                float sA = __fadd_rn(__fsub_rn(rrE, __fmul_rn(2.0f, dA)),
                                     __ldg(g_cnorms_em + q*Kk + i1));
                float sB = __fadd_rn(__fsub_rn(rrE, __fmul_rn(2.0f, dB)),
                                     __ldg(g_cnorms_em + q*Kk + i2));
                if (sB < sA || (sB == sA && i2 < i1)) chosen = i2;
            }
            sidx[tid] = chosen;
            sall[q*MT + tid] = chosen;
        }
        __syncthreads();

        // ---- residual update + new ||r||^2 (loss contribution; fast scheme)
        {
            const int urow = tid >> 2, uq = tid & 3, d0 = uq * 128;
            const int best = sidx[urow];
            const float4* cp = (const float4*)(cbq + (size_t)best * Dd + d0);
            float4* rp = (float4*)(rs + urow * RSTRIDE + d0);
            float ss = 0.f;
            #pragma unroll 8
            for (int jj = 0; jj < 32; jj++) {
                float4 c = __ldg(cp + jj);
                float4 r = rp[jj];
                r.x = __fsub_rn(r.x, c.x); r.y = __fsub_rn(r.y, c.y);
                r.z = __fsub_rn(r.z, c.z); r.w = __fsub_rn(r.w, c.w);
                rp[jj] = r;
                ss = fmaf(r.x, r.x, ss); ss = fmaf(r.y, r.y, ss);
                ss = fmaf(r.z, r.z, ss); ss = fmaf(r.w, r.w, ss);
            }
            swp[urow*4 + uq] = ss;
        }
        __syncthreads();
        if (tid < MT) srr[tid] = ((swp[tid*4] + swp[tid*4+1]) + swp[tid*4+2]) + swp[tid*4+3];
        __syncthreads();
        if (tid == 0) {
            float t = 0.f;
            for (int i = 0; i < MT; i++) t += srr[i];
            loss_acc += t;
        }
        __syncthreads();
    }
    if (tid == 0) g_losspart[blockIdx.x] = loss_acc;
    __syncthreads();

    // ---- epilogue: indices + quantized_st
    const size_t QUANT = (size_t)Nn * Dd;                 // 8388608
    const bool has_idx = out_size >= (int)(QUANT + (size_t)Bq*Qq*Tt);
    if (has_idx) {
        for (int e = tid; e < MT * Qq; e += NTHR) {
            int r = e & (MT - 1), q = e >> 6;
            int g = row0 + r, b = g >> 10, t = g & (Tt - 1);
            out[QUANT + (size_t)b*Qq*Tt + q*Tt + t] = (float)sall[q*MT + r];
        }
    }
    {
        const int urow = tid >> 2, uq = tid & 3, d0 = uq * 128;
        const int g = row0 + urow;
        int bidx[8];
        #pragma unroll
        for (int q = 0; q < Qq; q++) bidx[q] = sall[q*MT + urow];
        const float4* zp = (const float4*)(z + (size_t)g * Dd + d0);
        float4* op = (float4*)(out + (size_t)g * Dd + d0);
        for (int jj = 0; jj < 32; jj++) {
            float4 zv = __ldg(zp + jj);
            float qx = 0.f, qy = 0.f, qz = 0.f, qw = 0.f;
            #pragma unroll
            for (int q = 0; q < Qq; q++) {
                float4 c = __ldg((const float4*)(cb + ((size_t)q*Kk + bidx[q]) * Dd + d0) + jj);
                qx = __fadd_rn(qx, c.x); qy = __fadd_rn(qy, c.y);
                qz = __fadd_rn(qz, c.z); qw = __fadd_rn(qw, c.w);
            }
            float4 o;
            o.x = __fadd_rn(zv.x, __fsub_rn(qx, zv.x));
            o.y = __fadd_rn(zv.y, __fsub_rn(qy, zv.y));
            o.z = __fadd_rn(zv.z, __fsub_rn(qz, zv.z));
            o.w = __fadd_rn(zv.w, __fsub_rn(qw, zv.w));
            op[jj] = o;
        }
    }
}

// ---------------------------------------------------------------- loss reduce
__global__ void __launch_bounds__(NTHR) loss_kernel(float* __restrict__ out, int out_size) {
    __shared__ double sd[NTHR];
    int tid = threadIdx.x;
    double v = 0.0;
    for (int i = tid; i < NCTA; i += NTHR) v += (double)g_losspart[i];
    sd[tid] = v;
    __syncthreads();
    for (int o = NTHR/2; o > 0; o >>= 1) {
        if (tid < o) sd[tid] += sd[tid + o];
        __syncthreads();
    }
    if (tid == 0) {
        size_t pos = (size_t)Nn * Dd + (size_t)Bq * Qq * Tt;   // 8519680
        if (out_size > (int)pos)
            out[pos] = (float)(sd[0] / ((double)Nn * Dd * Qq));
    }
}

extern "C" void kernel_launch(void* const* d_in, const int* in_sizes, int n_in,
                              void* d_out, int out_size) {
    const float* z  = (const float*)d_in[0];
    const float* cb = (const float*)d_in[1];
    float* out = (float*)d_out;

    cudaFuncAttributes fa;
    if (cudaFuncGetAttributes(&fa, rvq_kernel) == cudaSuccess &&
        fa.maxDynamicSharedSizeBytes < (int)SMEM_BYTES) {
        cudaFuncSetAttribute(rvq_kernel, cudaFuncAttributeMaxDynamicSharedMemorySize,
                             (int)SMEM_BYTES);
    }

    cnorm_kernel<<<(Qq * Kk + 255) / 256, 256>>>(cb);
    cnorm_em_kernel<<<(Qq * Kk + 255) / 256, 256>>>(cb);
    rvq_kernel<<<NCTA, NTHR, SMEM_BYTES>>>(z, cb, out, out_size);
    loss_kernel<<<1, NTHR>>>(out, out_size);
}

// round 9
// speedup vs baseline: 1.0659x; 1.0659x over previous
#include <cuda_runtime.h>
#include <cstdint>

#define Bq 16
#define Tt 1024
#define Dd 512
#define Kk 1024
#define Qq 8
#define Nn (Bq*Tt)        // 16384 rows
#define MT 64             // rows per CTA
#define NT 256            // codes per tile (8 per lane)
#define NTILES (Kk/NT)    // 4
#define DC 32             // d-chunk
#define NTHR 256
#define NCTA (Nn/MT)      // 256
#define RSTRIDE 516       // residual row stride (floats), pad 4
#define CS2STRIDE 17      // code tile row stride in float2 (16 data + 1 pad)
#define REFINE_THR 4.0e-3f

// smem float counts
#define CS2B_F2 (NT*CS2STRIDE)         // float2 per buffer = 4352
#define CS2_F   (2*CS2B_F2*2)          // floats, both buffers = 17408
#define RS_F    (MT*RSTRIDE)           // 33024
#define SMEM_FLOATS (CS2_F + RS_F + MT + MT*4 + MT + MT)
#define SMEM_INTS   (MT + MT + MT + Qq*MT)
#define SMEM_BYTES  ((SMEM_FLOATS + SMEM_INTS)*4)   // 206336

__device__ float g_cnorms[Qq*Kk];      // fast-path norms (accurate scheme)
__device__ float g_cnorms_em[Qq*Kk];   // emulated XLA-CPU order: sequential mul+add
__device__ float g_losspart[NCTA];

#define FMA2(acc, x, y) asm("fma.rn.f32x2 %0, %1, %2, %0;" : "+l"(acc) : "l"(x), "l"(y))

// ---------------------------------------------------------------- codebook norms
// fast norms: compensated (accurate; used only for fast candidate scores)
__global__ void __launch_bounds__(256) cnorm_kernel(const float* __restrict__ cb) {
    int idx = blockIdx.x * blockDim.x + threadIdx.x;
    if (idx >= Qq * Kk) return;
    const float* row = cb + (size_t)idx * Dd;
    float s = 0.f, comp = 0.f;
    #pragma unroll 4
    for (int d = 0; d < Dd; d++) {
        float v = __ldg(row + d);
        float p  = __fmul_rn(v, v);
        float ep = __fmaf_rn(v, v, -p);
        float t  = __fadd_rn(s, p);
        float bb = __fsub_rn(t, s);
        float es = __fadd_rn(__fsub_rn(s, __fsub_rn(t, bb)), __fsub_rn(p, bb));
        s = t;
        comp = __fadd_rn(comp, __fadd_rn(ep, es));
    }
    g_cnorms[idx] = __fadd_rn(s, comp);
}

// emulated norms: XLA:CPU reduce = strict sequential scalar  s = s + x*x  (no fma)
__global__ void __launch_bounds__(256) cnorm_em_kernel(const float* __restrict__ cb) {
    int idx = blockIdx.x * blockDim.x + threadIdx.x;
    if (idx >= Qq * Kk) return;
    const float* row = cb + (size_t)idx * Dd;
    float s = 0.f;
    for (int d = 0; d < Dd; d++) {
        float v = __ldg(row + d);
        s = __fadd_rn(s, __fmul_rn(v, v));
    }
    g_cnorms_em[idx] = s;
}

// ---------------------------------------------------------------- main RVQ
__global__ void __launch_bounds__(NTHR, 1) rvq_kernel(
    const float* __restrict__ z, const float* __restrict__ cb,
    float* __restrict__ out, int out_size)
{
    extern __shared__ float smf[];
    float2* cs2  = (float2*)smf;                 // [2][NT][CS2STRIDE] float2
    float*  rs   = smf + CS2_F;                  // [MT][RSTRIDE]
    float*  srr  = rs + RS_F;                    // [MT]
    float*  swp  = srr + MT;                     // [MT][4]
    float*  s1v  = swp + MT*4;                   // [MT]
    float*  s2v  = s1v + MT;                     // [MT]
    int*    s1i  = (int*)(s2v + MT);             // [MT]
    int*    s2i  = s1i + MT;                     // [MT]
    int*    sidx = s2i + MT;                     // [MT]
    int*    sall = sidx + MT;                    // [Qq][MT]

    const int tid  = threadIdx.x;
    const int lane = tid & 31;
    const int wid  = tid >> 5;
    const int row0 = blockIdx.x * MT;

    // ---- load z rows into smem + initial per-row ||r||^2 (fast scheme)
    {
        const int urow = tid >> 2, uq = tid & 3, d0 = uq * 128;
        const float4* zsrc = (const float4*)(z + (size_t)(row0 + urow) * Dd + d0);
        float4* rdst = (float4*)(rs + urow * RSTRIDE + d0);
        float ss = 0.f;
        #pragma unroll 8
        for (int j = 0; j < 32; j++) {
            float4 v = __ldg(zsrc + j);
            rdst[j] = v;
            ss = fmaf(v.x, v.x, ss); ss = fmaf(v.y, v.y, ss);
            ss = fmaf(v.z, v.z, ss); ss = fmaf(v.w, v.w, ss);
        }
        swp[urow * 4 + uq] = ss;
    }
    __syncthreads();
    if (tid < MT) srr[tid] = ((swp[tid*4] + swp[tid*4+1]) + swp[tid*4+2]) + swp[tid*4+3];
    __syncthreads();

    float loss_acc = 0.f;

    for (int q = 0; q < Qq; q++) {
        const float* cbq = cb + (size_t)q * Kk * Dd;
        const float* cnq = g_cnorms + q * Kk;

        // per-lane running top-2 per row
        float t1v[8], t2v[8]; int t1i[8], t2i[8];
        #pragma unroll
        for (int i = 0; i < 8; i++) {
            t1v[i] = 3.4e38f; t1i[i] = 0x7fffffff;
            t2v[i] = 3.4e38f; t2i[i] = 0x7ffffffe;
        }

        for (int nt = 0; nt < NTILES; nt++) {
            const int k0 = nt * NT;

            unsigned long long acc[8][8];
            #pragma unroll
            for (int i = 0; i < 8; i++)
                #pragma unroll
                for (int j = 0; j < 8; j++) acc[i][j] = 0ULL;

            // ---- prologue: stage chunk 0 into buffer 0
            {
                float2* buf = cs2;   // buffer 0
                #pragma unroll
                for (int it = 0; it < 8; it++) {
                    int linI = tid + it * NTHR;             // 0..2047
                    int k = linI >> 3, d4 = linI & 7;
                    float4 v = __ldg((const float4*)(cbq + (size_t)(k0 + k) * Dd + d4*4));
                    buf[k * CS2STRIDE + d4*2    ] = make_float2(v.x, v.y);
                    buf[k * CS2STRIDE + d4*2 + 1] = make_float2(v.z, v.w);
                }
            }
            __syncthreads();

            for (int dc = 0; dc < Dd / DC; dc++) {
                const int cur = dc & 1;
                const unsigned long long* csu  =
                    (const unsigned long long*)(cs2 + cur * CS2B_F2);
                const unsigned long long* rbas = (const unsigned long long*)rs;

                #pragma unroll
                for (int dd = 0; dd < DC/2; dd++) {
                    unsigned long long rv[8];
                    #pragma unroll
                    for (int i = 0; i < 8; i++)
                        rv[i] = rbas[(wid*8 + i) * (RSTRIDE/2) + dc*(DC/2) + dd];
                    unsigned long long cv[8];
                    #pragma unroll
                    for (int j = 0; j < 8; j++)
                        cv[j] = csu[(lane + 32*j) * CS2STRIDE + dd];
                    #pragma unroll
                    for (int i = 0; i < 8; i++)
                        #pragma unroll
                        for (int j = 0; j < 8; j++)
                            FMA2(acc[i][j], rv[i], cv[j]);
                }

                // ---- stage next chunk into the other buffer (after compute;
                //      safe: its previous readers passed the last barrier)
                if (dc + 1 < Dd / DC) {
                    float2* buf = cs2 + (cur ^ 1) * CS2B_F2;
                    #pragma unroll
                    for (int it = 0; it < 8; it++) {
                        int linI = tid + it * NTHR;
                        int k = linI >> 3, d4 = linI & 7;
                        float4 v = __ldg((const float4*)(cbq + (size_t)(k0 + k) * Dd
                                                         + (dc+1)*DC + d4*4));
                        buf[k * CS2STRIDE + d4*2    ] = make_float2(v.x, v.y);
                        buf[k * CS2STRIDE + d4*2 + 1] = make_float2(v.z, v.w);
                    }
                }
                __syncthreads();
            }

            // ---- fast scores; insert into per-lane top-2
            #pragma unroll
            for (int i = 0; i < 8; i++) {
                float rr = srr[wid*8 + i];
                #pragma unroll
                for (int j = 0; j < 8; j++) {
                    unsigned int lo, hi;
                    asm("mov.b64 {%0,%1}, %2;" : "=r"(lo), "=r"(hi) : "l"(acc[i][j]));
                    float dot = __fadd_rn(__uint_as_float(lo), __uint_as_float(hi));
                    float s = __fadd_rn(__fsub_rn(rr, __fmul_rn(2.0f, dot)),
                                        __ldg(cnq + k0 + lane + 32*j));
                    int k = k0 + lane + 32*j;
                    if (s < t1v[i] || (s == t1v[i] && k < t1i[i])) {
                        t2v[i] = t1v[i]; t2i[i] = t1i[i];
                        t1v[i] = s;      t1i[i] = k;
                    } else if (s < t2v[i] || (s == t2v[i] && k < t2i[i])) {
                        t2v[i] = s; t2i[i] = k;
                    }
                }
            }
        }

        // ---- warp butterfly top-2 merge, write to smem
        #pragma unroll
        for (int i = 0; i < 8; i++) {
            float v1 = t1v[i]; int i1 = t1i[i];
            float v2 = t2v[i]; int i2 = t2i[i];
            #pragma unroll
            for (int off = 16; off > 0; off >>= 1) {
                float w1 = __shfl_xor_sync(0xffffffffu, v1, off);
                int   j1 = __shfl_xor_sync(0xffffffffu, i1, off);
                float w2 = __shfl_xor_sync(0xffffffffu, v2, off);
                int   j2 = __shfl_xor_sync(0xffffffffu, i2, off);
                if (w1 < v1 || (w1 == v1 && j1 < i1)) {
                    bool a_over_b2 = (v1 < w2 || (v1 == w2 && i1 < j2));
                    float nv2 = a_over_b2 ? v1 : w2;
                    int   ni2 = a_over_b2 ? i1 : j2;
                    v2 = nv2; i2 = ni2; v1 = w1; i1 = j1;
                } else if (w1 < v2 || (w1 == v2 && j1 < i2)) {
                    v2 = w1; i2 = j1;
                }
            }
            if (lane == 0) {
                s1v[wid*8+i] = v1; s1i[wid*8+i] = i1;
                s2v[wid*8+i] = v2; s2i[wid*8+i] = i2;
            }
        }
        __syncthreads();

        // ---- near-tie re-decision with EMULATED reference arithmetic
        // (XLA:CPU: rr = sequential scalar s+x*x; dot = Eigen SGEMM strict
        //  ascending-k fma chain; score tree (rr - 2*dot) + cn; low-index tie.)
        if (tid < MT) {
            float v1 = s1v[tid]; int i1 = s1i[tid];
            float v2 = s2v[tid]; int i2 = s2i[tid];
            int chosen = i1;
            if (__fsub_rn(v2, v1) <= REFINE_THR) {
                const float* rrow = rs + tid * RSTRIDE;
                float rrE = 0.f;
                for (int d = 0; d < Dd; d++)
                    rrE = __fadd_rn(rrE, __fmul_rn(rrow[d], rrow[d]));
                const float* cA = cbq + (size_t)i1 * Dd;
                const float* cB = cbq + (size_t)i2 * Dd;
                float dA = 0.f, dB = 0.f;
                for (int d = 0; d < Dd; d++) dA = __fmaf_rn(rrow[d], __ldg(cA + d), dA);
                for (int d = 0; d < Dd; d++) dB = __fmaf_rn(rrow[d], __ldg(cB + d), dB);
                float sA = __fadd_rn(__fsub_rn(rrE, __fmul_rn(2.0f, dA)),
                                     __ldg(g_cnorms_em + q*Kk + i1));
                float sB = __fadd_rn(__fsub_rn(rrE, __fmul_rn(2.0f, dB)),
                                     __ldg(g_cnorms_em + q*Kk + i2));
                if (sB < sA || (sB == sA && i2 < i1)) chosen = i2;
            }
            sidx[tid] = chosen;
            sall[q*MT + tid] = chosen;
        }
        __syncthreads();

        // ---- residual update + new ||r||^2 (loss contribution; fast scheme)
        {
            const int urow = tid >> 2, uq = tid & 3, d0 = uq * 128;
            const int best = sidx[urow];
            const float4* cp = (const float4*)(cbq + (size_t)best * Dd + d0);
            float4* rp = (float4*)(rs + urow * RSTRIDE + d0);
            float ss = 0.f;
            #pragma unroll 8
            for (int jj = 0; jj < 32; jj++) {
                float4 c = __ldg(cp + jj);
                float4 r = rp[jj];
                r.x = __fsub_rn(r.x, c.x); r.y = __fsub_rn(r.y, c.y);
                r.z = __fsub_rn(r.z, c.z); r.w = __fsub_rn(r.w, c.w);
                rp[jj] = r;
                ss = fmaf(r.x, r.x, ss); ss = fmaf(r.y, r.y, ss);
                ss = fmaf(r.z, r.z, ss); ss = fmaf(r.w, r.w, ss);
            }
            swp[urow*4 + uq] = ss;
        }
        __syncthreads();
        if (tid < MT) srr[tid] = ((swp[tid*4] + swp[tid*4+1]) + swp[tid*4+2]) + swp[tid*4+3];
        __syncthreads();
        if (tid == 0) {
            float t = 0.f;
            for (int i = 0; i < MT; i++) t += srr[i];
            loss_acc += t;
        }
        __syncthreads();
    }
    if (tid == 0) g_losspart[blockIdx.x] = loss_acc;
    __syncthreads();

    // ---- epilogue: indices + quantized_st
    const size_t QUANT = (size_t)Nn * Dd;                 // 8388608
    const bool has_idx = out_size >= (int)(QUANT + (size_t)Bq*Qq*Tt);
    if (has_idx) {
        for (int e = tid; e < MT * Qq; e += NTHR) {
            int r = e & (MT - 1), q = e >> 6;
            int g = row0 + r, b = g >> 10, t = g & (Tt - 1);
            out[QUANT + (size_t)b*Qq*Tt + q*Tt + t] = (float)sall[q*MT + r];
        }
    }
    {
        const int urow = tid >> 2, uq = tid & 3, d0 = uq * 128;
        const int g = row0 + urow;
        int bidx[8];
        #pragma unroll
        for (int q = 0; q < Qq; q++) bidx[q] = sall[q*MT + urow];
        const float4* zp = (const float4*)(z + (size_t)g * Dd + d0);
        float4* op = (float4*)(out + (size_t)g * Dd + d0);
        for (int jj = 0; jj < 32; jj++) {
            float4 zv = __ldg(zp + jj);
            float qx = 0.f, qy = 0.f, qz = 0.f, qw = 0.f;
            #pragma unroll
            for (int q = 0; q < Qq; q++) {
                float4 c = __ldg((const float4*)(cb + ((size_t)q*Kk + bidx[q]) * Dd + d0) + jj);
                qx = __fadd_rn(qx, c.x); qy = __fadd_rn(qy, c.y);
                qz = __fadd_rn(qz, c.z); qw = __fadd_rn(qw, c.w);
            }
            float4 o;
            o.x = __fadd_rn(zv.x, __fsub_rn(qx, zv.x));
            o.y = __fadd_rn(zv.y, __fsub_rn(qy, zv.y));
            o.z = __fadd_rn(zv.z, __fsub_rn(qz, zv.z));
            o.w = __fadd_rn(zv.w, __fsub_rn(qw, zv.w));
            op[jj] = o;
        }
    }
}

// ---------------------------------------------------------------- loss reduce
__global__ void __launch_bounds__(NTHR) loss_kernel(float* __restrict__ out, int out_size) {
    __shared__ double sd[NTHR];
    int tid = threadIdx.x;
    double v = 0.0;
    for (int i = tid; i < NCTA; i += NTHR) v += (double)g_losspart[i];
    sd[tid] = v;
    __syncthreads();
    for (int o = NTHR/2; o > 0; o >>= 1) {
        if (tid < o) sd[tid] += sd[tid + o];
        __syncthreads();
    }
    if (tid == 0) {
        size_t pos = (size_t)Nn * Dd + (size_t)Bq * Qq * Tt;   // 8519680
        if (out_size > (int)pos)
            out[pos] = (float)(sd[0] / ((double)Nn * Dd * Qq));
    }
}

extern "C" void kernel_launch(void* const* d_in, const int* in_sizes, int n_in,
                              void* d_out, int out_size) {
    const float* z  = (const float*)d_in[0];
    const float* cb = (const float*)d_in[1];
    float* out = (float*)d_out;

    cudaFuncAttributes fa;
    if (cudaFuncGetAttributes(&fa, rvq_kernel) == cudaSuccess &&
        fa.maxDynamicSharedSizeBytes < (int)SMEM_BYTES) {
        cudaFuncSetAttribute(rvq_kernel, cudaFuncAttributeMaxDynamicSharedMemorySize,
                             (int)SMEM_BYTES);
    }

    cnorm_kernel<<<(Qq * Kk + 255) / 256, 256>>>(cb);
    cnorm_em_kernel<<<(Qq * Kk + 255) / 256, 256>>>(cb);
    rvq_kernel<<<NCTA, NTHR, SMEM_BYTES>>>(z, cb, out, out_size);
    loss_kernel<<<1, NTHR>>>(out, out_size);
}